// round 12
// baseline (speedup 1.0000x reference)
#include <cuda_runtime.h>
#include <cuda_fp16.h>
#include <stdint.h>

#define F_IN 128
#define HID  16
#define NCLS 8
#define MAX_N 100000

__device__ float  g_deg [MAX_N];
__device__ float  g_dinv[MAX_N];
__device__ __half g_h1h [MAX_N * HID];   // fp16 dinv*(x@W1), gathered by edge1
__device__ float  g_agg1[MAX_N * HID];   // fp32 accumulator (self-loop init)
__device__ __half g_h2h [MAX_N * NCLS];  // fp16 dinv*h2, gathered by edge2
__device__ float  g_agg2[MAX_N * NCLS];

__device__ __forceinline__ void red_add_v4(float* p, float4 v) {
    asm volatile("red.global.add.v4.f32 [%0], {%1, %2, %3, %4};"
                 :: "l"(p), "f"(v.x), "f"(v.y), "f"(v.z), "f"(v.w) : "memory");
}

// 0) deg init: self-loop contributes 1
__global__ void k_init_deg(int n) {
    int i = blockIdx.x * blockDim.x + threadIdx.x;
    if (i < n) g_deg[i] = 1.0f;
}

// 1) degree scatter, int4-vectorized (4 edges per thread)
__global__ void k_deg_scatter(const int* __restrict__ dst, int e) {
    int i = blockIdx.x * blockDim.x + threadIdx.x;
    int e4 = e >> 2;
    if (i < e4) {
        int4 d = ((const int4*)dst)[i];
        atomicAdd(&g_deg[d.x], 1.0f);
        atomicAdd(&g_deg[d.y], 1.0f);
        atomicAdd(&g_deg[d.z], 1.0f);
        atomicAdd(&g_deg[d.w], 1.0f);
    } else {
        int base = e4 * 4 + (i - e4);
        if (base < e) atomicAdd(&g_deg[dst[base]], 1.0f);
    }
}

// 2) xw1 fused (W-amortized, dinv inline): thread = (slot, jg), 4 nodes x 4 out.
//    agg1 = fp32 self term; h1h = fp16 copy for gathering.
#define XW_ND 4
__global__ void __launch_bounds__(256, 4) k_xw1(const float* __restrict__ x,
                                                const float* __restrict__ W1, int n) {
    __shared__ float4 sW1[F_IN * 4];  // sW1[k*4+jg] = W1[k][4jg..4jg+3]
    int t = threadIdx.x;
    for (int i = t; i < F_IN * 4; i += blockDim.x)
        sW1[i] = ((const float4*)W1)[i];
    __syncthreads();

    int slot = t >> 2;            // 0..63
    int jg   = t & 3;             // 0..3
    int base = blockIdx.x * (64 * XW_ND);

    int  node[XW_ND];
    bool ok  [XW_ND];
    #pragma unroll
    for (int i = 0; i < XW_ND; i++) {
        node[i] = base + i * 64 + slot;
        ok[i]   = node[i] < n;
    }

    float4 acc[XW_ND];
    #pragma unroll
    for (int i = 0; i < XW_ND; i++) acc[i] = make_float4(0.f, 0.f, 0.f, 0.f);

    #pragma unroll 4
    for (int k4 = 0; k4 < F_IN / 4; k4++) {
        float4 w0 = sW1[(k4 * 4 + 0) * 4 + jg];
        float4 w1 = sW1[(k4 * 4 + 1) * 4 + jg];
        float4 w2 = sW1[(k4 * 4 + 2) * 4 + jg];
        float4 w3 = sW1[(k4 * 4 + 3) * 4 + jg];
        float4 xv[XW_ND];
        #pragma unroll
        for (int i = 0; i < XW_ND; i++)
            xv[i] = ok[i] ? __ldg((const float4*)(x + (size_t)node[i] * F_IN) + k4)
                          : make_float4(0.f, 0.f, 0.f, 0.f);
        #pragma unroll
        for (int i = 0; i < XW_ND; i++) {
            acc[i].x = fmaf(xv[i].x, w0.x, acc[i].x);
            acc[i].y = fmaf(xv[i].x, w0.y, acc[i].y);
            acc[i].z = fmaf(xv[i].x, w0.z, acc[i].z);
            acc[i].w = fmaf(xv[i].x, w0.w, acc[i].w);
            acc[i].x = fmaf(xv[i].y, w1.x, acc[i].x);
            acc[i].y = fmaf(xv[i].y, w1.y, acc[i].y);
            acc[i].z = fmaf(xv[i].y, w1.z, acc[i].z);
            acc[i].w = fmaf(xv[i].y, w1.w, acc[i].w);
            acc[i].x = fmaf(xv[i].z, w2.x, acc[i].x);
            acc[i].y = fmaf(xv[i].z, w2.y, acc[i].y);
            acc[i].z = fmaf(xv[i].z, w2.z, acc[i].z);
            acc[i].w = fmaf(xv[i].z, w2.w, acc[i].w);
            acc[i].x = fmaf(xv[i].w, w3.x, acc[i].x);
            acc[i].y = fmaf(xv[i].w, w3.y, acc[i].y);
            acc[i].z = fmaf(xv[i].w, w3.z, acc[i].z);
            acc[i].w = fmaf(xv[i].w, w3.w, acc[i].w);
        }
    }

    #pragma unroll
    for (int i = 0; i < XW_ND; i++) {
        if (!ok[i]) continue;
        float di = rsqrtf(g_deg[node[i]]);
        if (jg == 0) g_dinv[node[i]] = di;
        float4 hs = make_float4(di * acc[i].x, di * acc[i].y,
                                di * acc[i].z, di * acc[i].w);
        *(float4*)(g_agg1 + node[i] * HID + jg * 4) = hs;   // fp32 self term
        __half2 p0 = __floats2half2_rn(hs.x, hs.y);
        __half2 p1 = __floats2half2_rn(hs.z, hs.w);
        uint2 u;
        u.x = *(unsigned*)&p0;
        u.y = *(unsigned*)&p1;
        *(uint2*)(g_h1h + node[i] * HID + jg * 4) = u;      // fp16 gather copy
    }
}

// 3) layer-1 edge scatter: 2 threads/edge (j=0,1), 2 edges/thread.
//    fp16 gather (LDG.128 = 8 halves), fp32 v4 RED x2.  [profiled idx 3]
__global__ void k_edge1(const int* __restrict__ src,
                        const int* __restrict__ dst, int e) {
    int h = (e + 1) >> 1;
    long long gid = (long long)blockIdx.x * blockDim.x + threadIdx.x;
    int q = (int)(gid >> 1);
    int j = (int)(gid & 1);
    if (q >= h) return;
    int eA = q, eB = q + h;
    bool hasB = eB < e;

    int sA = src[eA], dA = dst[eA];
    int sB = 0, dB = 0;
    if (hasB) { sB = src[eB]; dB = dst[eB]; }

    uint4 pA = *(const uint4*)(g_h1h + sA * HID + j * 8);
    uint4 pB = hasB ? *(const uint4*)(g_h1h + sB * HID + j * 8)
                    : make_uint4(0, 0, 0, 0);

    {
        float2 f0 = __half22float2(*(__half2*)&pA.x);
        float2 f1 = __half22float2(*(__half2*)&pA.y);
        float2 f2 = __half22float2(*(__half2*)&pA.z);
        float2 f3 = __half22float2(*(__half2*)&pA.w);
        red_add_v4(g_agg1 + dA * HID + j * 8,     make_float4(f0.x, f0.y, f1.x, f1.y));
        red_add_v4(g_agg1 + dA * HID + j * 8 + 4, make_float4(f2.x, f2.y, f3.x, f3.y));
    }
    if (hasB) {
        float2 f0 = __half22float2(*(__half2*)&pB.x);
        float2 f1 = __half22float2(*(__half2*)&pB.y);
        float2 f2 = __half22float2(*(__half2*)&pB.z);
        float2 f3 = __half22float2(*(__half2*)&pB.w);
        red_add_v4(g_agg1 + dB * HID + j * 8,     make_float4(f0.x, f0.y, f1.x, f1.y));
        red_add_v4(g_agg1 + dB * HID + j * 8 + 4, make_float4(f2.x, f2.y, f3.x, f3.y));
    }
}

// 4) h2 = relu(dinv*agg1 + b1) @ W2; agg2 = fp32 self term; h2h = fp16 copy
__global__ void k_layer2(const float* __restrict__ b1,
                         const float* __restrict__ W2, int n) {
    __shared__ float sW2[HID * NCLS];
    __shared__ float sb1[HID];
    if (threadIdx.x < HID * NCLS) sW2[threadIdx.x] = W2[threadIdx.x];
    if (threadIdx.x < HID) sb1[threadIdx.x] = b1[threadIdx.x];
    __syncthreads();

    int gid = blockIdx.x * blockDim.x + threadIdx.x;
    int node = gid / NCLS;
    int c    = gid % NCLS;
    if (node >= n) return;

    float di = g_dinv[node];
    float acc = 0.0f;
    #pragma unroll
    for (int j = 0; j < HID; j++) {
        float v = fmaf(di, g_agg1[node * HID + j], sb1[j]);
        v = fmaxf(v, 0.0f);
        acc = fmaf(v, sW2[j * NCLS + c], acc);
    }
    float hs = di * acc;
    g_agg2[node * NCLS + c] = hs;
    g_h2h [node * NCLS + c] = __float2half_rn(hs);
}

// 5) layer-2 edge scatter: 1 thread/edge, 2 edges/thread.
//    fp16 gather (LDG.128 = 8 halves), fp32 v4 RED x2.
__global__ void k_edge2(const int* __restrict__ src,
                        const int* __restrict__ dst, int e) {
    int h = (e + 1) >> 1;
    long long gid = (long long)blockIdx.x * blockDim.x + threadIdx.x;
    int q = (int)gid;
    if (q >= h) return;
    int eA = q, eB = q + h;
    bool hasB = eB < e;

    int sA = src[eA], dA = dst[eA];
    int sB = 0, dB = 0;
    if (hasB) { sB = src[eB]; dB = dst[eB]; }

    uint4 pA = *(const uint4*)(g_h2h + sA * NCLS);
    uint4 pB = hasB ? *(const uint4*)(g_h2h + sB * NCLS)
                    : make_uint4(0, 0, 0, 0);

    {
        float2 f0 = __half22float2(*(__half2*)&pA.x);
        float2 f1 = __half22float2(*(__half2*)&pA.y);
        float2 f2 = __half22float2(*(__half2*)&pA.z);
        float2 f3 = __half22float2(*(__half2*)&pA.w);
        red_add_v4(g_agg2 + dA * NCLS,     make_float4(f0.x, f0.y, f1.x, f1.y));
        red_add_v4(g_agg2 + dA * NCLS + 4, make_float4(f2.x, f2.y, f3.x, f3.y));
    }
    if (hasB) {
        float2 f0 = __half22float2(*(__half2*)&pB.x);
        float2 f1 = __half22float2(*(__half2*)&pB.y);
        float2 f2 = __half22float2(*(__half2*)&pB.z);
        float2 f3 = __half22float2(*(__half2*)&pB.w);
        red_add_v4(g_agg2 + dB * NCLS,     make_float4(f0.x, f0.y, f1.x, f1.y));
        red_add_v4(g_agg2 + dB * NCLS + 4, make_float4(f2.x, f2.y, f3.x, f3.y));
    }
}

// 6) logits = dinv*agg2 + b2 -> log_softmax
__global__ void k_logsoftmax(const float* __restrict__ b2,
                             float* __restrict__ out, int n) {
    __shared__ float sb2[NCLS];
    if (threadIdx.x < NCLS) sb2[threadIdx.x] = b2[threadIdx.x];
    __syncthreads();

    int i = blockIdx.x * blockDim.x + threadIdx.x;
    if (i >= n) return;

    float di = g_dinv[i];
    float4 a = *(const float4*)(g_agg2 + i * NCLS);
    float4 b = *(const float4*)(g_agg2 + i * NCLS + 4);
    float z[NCLS] = {fmaf(di, a.x, sb2[0]), fmaf(di, a.y, sb2[1]),
                     fmaf(di, a.z, sb2[2]), fmaf(di, a.w, sb2[3]),
                     fmaf(di, b.x, sb2[4]), fmaf(di, b.y, sb2[5]),
                     fmaf(di, b.z, sb2[6]), fmaf(di, b.w, sb2[7])};
    float m = z[0];
    #pragma unroll
    for (int c = 1; c < NCLS; c++) m = fmaxf(m, z[c]);
    float sum = 0.0f;
    #pragma unroll
    for (int c = 0; c < NCLS; c++) sum += expf(z[c] - m);
    float lse = m + logf(sum);
    *(float4*)(out + i * NCLS)     = make_float4(z[0]-lse, z[1]-lse, z[2]-lse, z[3]-lse);
    *(float4*)(out + i * NCLS + 4) = make_float4(z[4]-lse, z[5]-lse, z[6]-lse, z[7]-lse);
}

// ---------------------------------------------------------------------------
extern "C" void kernel_launch(void* const* d_in, const int* in_sizes, int n_in,
                              void* d_out, int out_size) {
    const float* x  = (const float*)d_in[0];
    const int*   ei = (const int*)d_in[1];    // [2, E] int32
    const float* W1 = (const float*)d_in[2];
    const float* b1 = (const float*)d_in[3];
    const float* W2 = (const float*)d_in[4];
    const float* b2 = (const float*)d_in[5];
    float*       out = (float*)d_out;

    const int n = in_sizes[0] / F_IN;      // 100000
    const int e = in_sizes[1] / 2;         // 3200000
    const int* src = ei;
    const int* dst = ei + e;

    const int T = 256;
    int e4t = (e >> 2) + (e & 3);
    int h   = (e + 1) >> 1;

    k_init_deg<<<(n + T - 1) / T, T>>>(n);                              // 0
    k_deg_scatter<<<(e4t + T - 1) / T, T>>>(dst, e);                    // 1
    k_xw1<<<(n + 64 * XW_ND - 1) / (64 * XW_ND), T>>>(x, W1, n);        // 2
    {
        long long total = (long long)h * 2;
        k_edge1<<<(unsigned)((total + T - 1) / T), T>>>(src, dst, e);   // 3 (profiled)
    }
    k_layer2<<<((long long)n * NCLS + T - 1) / T, T>>>(b1, W2, n);      // 4
    k_edge2<<<(h + T - 1) / T, T>>>(src, dst, e);                       // 5
    k_logsoftmax<<<(n + T - 1) / T, T>>>(b2, out, n);                   // 6
}

// round 13
// speedup vs baseline: 1.0304x; 1.0304x over previous
#include <cuda_runtime.h>
#include <stdint.h>

#define F_IN 128
#define HID  16
#define NCLS 8
#define MAX_N 100000

__device__ float g_deg [MAX_N];
__device__ float g_dinv[MAX_N];
__device__ float g_h1  [MAX_N * HID];   // raw x@W1 (written by xw1_raw)
__device__ float g_h1s [MAX_N * HID];   // dinv * h1 (gathered by edge1)
__device__ float g_agg1[MAX_N * HID];   // fp32 accumulator (self-loop init)
__device__ float g_h2s [MAX_N * NCLS];  // dinv * h2 (gathered by edge2)
__device__ float g_agg2[MAX_N * NCLS];

__device__ __forceinline__ void red_add_v4(float* p, float4 v) {
    asm volatile("red.global.add.v4.f32 [%0], {%1, %2, %3, %4};"
                 :: "l"(p), "f"(v.x), "f"(v.y), "f"(v.z), "f"(v.w) : "memory");
}

// A0) deg init: self-loop contributes 1   [stream 2]
__global__ void k_init_deg(int n) {
    int i = blockIdx.x * blockDim.x + threadIdx.x;
    if (i < n) g_deg[i] = 1.0f;
}

// A1) degree scatter, int4-vectorized (4 edges per thread)   [stream 2]
__global__ void k_deg_scatter(const int* __restrict__ dst, int e) {
    int i = blockIdx.x * blockDim.x + threadIdx.x;
    int e4 = e >> 2;
    if (i < e4) {
        int4 d = ((const int4*)dst)[i];
        atomicAdd(&g_deg[d.x], 1.0f);
        atomicAdd(&g_deg[d.y], 1.0f);
        atomicAdd(&g_deg[d.z], 1.0f);
        atomicAdd(&g_deg[d.w], 1.0f);
    } else {
        int base = e4 * 4 + (i - e4);
        if (base < e) atomicAdd(&g_deg[dst[base]], 1.0f);
    }
}

// B0) xw1 raw GEMM (no deg dependency): thread = (slot, jg), 4 nodes x 4 out.
#define XW_ND 4
__global__ void __launch_bounds__(256, 4) k_xw1_raw(const float* __restrict__ x,
                                                    const float* __restrict__ W1, int n) {
    __shared__ float4 sW1[F_IN * 4];  // sW1[k*4+jg] = W1[k][4jg..4jg+3]
    int t = threadIdx.x;
    for (int i = t; i < F_IN * 4; i += blockDim.x)
        sW1[i] = ((const float4*)W1)[i];
    __syncthreads();

    int slot = t >> 2;            // 0..63
    int jg   = t & 3;             // 0..3
    int base = blockIdx.x * (64 * XW_ND);

    int  node[XW_ND];
    bool ok  [XW_ND];
    #pragma unroll
    for (int i = 0; i < XW_ND; i++) {
        node[i] = base + i * 64 + slot;
        ok[i]   = node[i] < n;
    }

    float4 acc[XW_ND];
    #pragma unroll
    for (int i = 0; i < XW_ND; i++) acc[i] = make_float4(0.f, 0.f, 0.f, 0.f);

    #pragma unroll 4
    for (int k4 = 0; k4 < F_IN / 4; k4++) {
        float4 w0 = sW1[(k4 * 4 + 0) * 4 + jg];
        float4 w1 = sW1[(k4 * 4 + 1) * 4 + jg];
        float4 w2 = sW1[(k4 * 4 + 2) * 4 + jg];
        float4 w3 = sW1[(k4 * 4 + 3) * 4 + jg];
        float4 xv[XW_ND];
        #pragma unroll
        for (int i = 0; i < XW_ND; i++)
            xv[i] = ok[i] ? __ldg((const float4*)(x + (size_t)node[i] * F_IN) + k4)
                          : make_float4(0.f, 0.f, 0.f, 0.f);
        #pragma unroll
        for (int i = 0; i < XW_ND; i++) {
            acc[i].x = fmaf(xv[i].x, w0.x, acc[i].x);
            acc[i].y = fmaf(xv[i].x, w0.y, acc[i].y);
            acc[i].z = fmaf(xv[i].x, w0.z, acc[i].z);
            acc[i].w = fmaf(xv[i].x, w0.w, acc[i].w);
            acc[i].x = fmaf(xv[i].y, w1.x, acc[i].x);
            acc[i].y = fmaf(xv[i].y, w1.y, acc[i].y);
            acc[i].z = fmaf(xv[i].y, w1.z, acc[i].z);
            acc[i].w = fmaf(xv[i].y, w1.w, acc[i].w);
            acc[i].x = fmaf(xv[i].z, w2.x, acc[i].x);
            acc[i].y = fmaf(xv[i].z, w2.y, acc[i].y);
            acc[i].z = fmaf(xv[i].z, w2.z, acc[i].z);
            acc[i].w = fmaf(xv[i].z, w2.w, acc[i].w);
            acc[i].x = fmaf(xv[i].w, w3.x, acc[i].x);
            acc[i].y = fmaf(xv[i].w, w3.y, acc[i].y);
            acc[i].z = fmaf(xv[i].w, w3.z, acc[i].z);
            acc[i].w = fmaf(xv[i].w, w3.w, acc[i].w);
        }
    }

    #pragma unroll
    for (int i = 0; i < XW_ND; i++)
        if (ok[i])
            *(float4*)(g_h1 + node[i] * HID + jg * 4) = acc[i];
}

// J0) scale (after join): dinv = rsqrt(deg); h1s = dinv*h1; agg1 = h1s
__global__ void k_scale(int n) {
    int tid = blockIdx.x * blockDim.x + threadIdx.x;
    int node = tid >> 2;
    int j    = tid & 3;
    if (node >= n) return;
    float di = rsqrtf(g_deg[node]);     // broadcast within 4-lane group
    if (j == 0) g_dinv[node] = di;
    float4 h = *(const float4*)(g_h1 + node * HID + j * 4);
    float4 hs = make_float4(di * h.x, di * h.y, di * h.z, di * h.w);
    *(float4*)(g_h1s  + node * HID + j * 4) = hs;
    *(float4*)(g_agg1 + node * HID + j * 4) = hs;
}

// E1) layer-1 edge scatter: 4 threads/edge, 2 edges/thread, v4 RED (fp32)
__global__ void k_edge1(const int* __restrict__ src,
                        const int* __restrict__ dst, int e) {
    int h = (e + 1) >> 1;
    long long gid = (long long)blockIdx.x * blockDim.x + threadIdx.x;
    int q = (int)(gid >> 2);
    int j = (int)(gid & 3);
    if (q >= h) return;
    int eA = q, eB = q + h;
    bool hasB = eB < e;

    int sA = src[eA], dA = dst[eA];
    int sB = 0, dB = 0;
    if (hasB) { sB = src[eB]; dB = dst[eB]; }

    float4 hA = *(const float4*)(g_h1s + sA * HID + j * 4);
    red_add_v4(g_agg1 + dA * HID + j * 4, hA);
    if (hasB) {
        float4 hB = *(const float4*)(g_h1s + sB * HID + j * 4);
        red_add_v4(g_agg1 + dB * HID + j * 4, hB);
    }
}

// L2) h2 = relu(dinv*agg1 + b1) @ W2; h2s = dinv*h2; agg2 = h2s (self loop)
__global__ void k_layer2(const float* __restrict__ b1,
                         const float* __restrict__ W2, int n) {
    __shared__ float sW2[HID * NCLS];
    __shared__ float sb1[HID];
    if (threadIdx.x < HID * NCLS) sW2[threadIdx.x] = W2[threadIdx.x];
    if (threadIdx.x < HID) sb1[threadIdx.x] = b1[threadIdx.x];
    __syncthreads();

    int gid = blockIdx.x * blockDim.x + threadIdx.x;
    int node = gid / NCLS;
    int c    = gid % NCLS;
    if (node >= n) return;

    float di = g_dinv[node];
    float acc = 0.0f;
    #pragma unroll
    for (int j = 0; j < HID; j++) {
        float v = fmaf(di, g_agg1[node * HID + j], sb1[j]);
        v = fmaxf(v, 0.0f);
        acc = fmaf(v, sW2[j * NCLS + c], acc);
    }
    float hs = di * acc;
    g_h2s [node * NCLS + c] = hs;
    g_agg2[node * NCLS + c] = hs;
}

// E2) layer-2 edge scatter: 2 threads/edge, 2 edges/thread, v4 RED (fp32)
__global__ void k_edge2(const int* __restrict__ src,
                        const int* __restrict__ dst, int e) {
    int h = (e + 1) >> 1;
    long long gid = (long long)blockIdx.x * blockDim.x + threadIdx.x;
    int q = (int)(gid >> 1);
    int j = (int)(gid & 1);
    if (q >= h) return;
    int eA = q, eB = q + h;
    bool hasB = eB < e;

    int sA = src[eA], dA = dst[eA];
    int sB = 0, dB = 0;
    if (hasB) { sB = src[eB]; dB = dst[eB]; }

    float4 hA = *(const float4*)(g_h2s + sA * NCLS + j * 4);
    red_add_v4(g_agg2 + dA * NCLS + j * 4, hA);
    if (hasB) {
        float4 hB = *(const float4*)(g_h2s + sB * NCLS + j * 4);
        red_add_v4(g_agg2 + dB * NCLS + j * 4, hB);
    }
}

// F) logits = dinv*agg2 + b2 -> log_softmax
__global__ void k_logsoftmax(const float* __restrict__ b2,
                             float* __restrict__ out, int n) {
    __shared__ float sb2[NCLS];
    if (threadIdx.x < NCLS) sb2[threadIdx.x] = b2[threadIdx.x];
    __syncthreads();

    int i = blockIdx.x * blockDim.x + threadIdx.x;
    if (i >= n) return;

    float di = g_dinv[i];
    float4 a = *(const float4*)(g_agg2 + i * NCLS);
    float4 b = *(const float4*)(g_agg2 + i * NCLS + 4);
    float z[NCLS] = {fmaf(di, a.x, sb2[0]), fmaf(di, a.y, sb2[1]),
                     fmaf(di, a.z, sb2[2]), fmaf(di, a.w, sb2[3]),
                     fmaf(di, b.x, sb2[4]), fmaf(di, b.y, sb2[5]),
                     fmaf(di, b.z, sb2[6]), fmaf(di, b.w, sb2[7])};
    float m = z[0];
    #pragma unroll
    for (int c = 1; c < NCLS; c++) m = fmaxf(m, z[c]);
    float sum = 0.0f;
    #pragma unroll
    for (int c = 0; c < NCLS; c++) sum += expf(z[c] - m);
    float lse = m + logf(sum);
    *(float4*)(out + i * NCLS)     = make_float4(z[0]-lse, z[1]-lse, z[2]-lse, z[3]-lse);
    *(float4*)(out + i * NCLS + 4) = make_float4(z[4]-lse, z[5]-lse, z[6]-lse, z[7]-lse);
}

// ---------------------------------------------------------------------------
extern "C" void kernel_launch(void* const* d_in, const int* in_sizes, int n_in,
                              void* d_out, int out_size) {
    const float* x  = (const float*)d_in[0];
    const int*   ei = (const int*)d_in[1];    // [2, E] int32
    const float* W1 = (const float*)d_in[2];
    const float* b1 = (const float*)d_in[3];
    const float* W2 = (const float*)d_in[4];
    const float* b2 = (const float*)d_in[5];
    float*       out = (float*)d_out;

    const int n = in_sizes[0] / F_IN;      // 100000
    const int e = in_sizes[1] / 2;         // 3200000
    const int* src = ei;
    const int* dst = ei + e;

    const int T = 256;
    int e4t = (e >> 2) + (e & 3);

    // One-time stream/event setup (outside first capture; no device allocs).
    static cudaStream_t s2 = nullptr;
    static cudaEvent_t  evFork = nullptr, evJoin = nullptr;
    if (s2 == nullptr) {
        cudaStreamCreateWithFlags(&s2, cudaStreamNonBlocking);
        cudaEventCreateWithFlags(&evFork, cudaEventDisableTiming);
        cudaEventCreateWithFlags(&evJoin, cudaEventDisableTiming);
    }

    // Fork: degree pipeline on s2, concurrent with xw1 raw GEMM on main stream.
    cudaEventRecord(evFork, 0);
    cudaStreamWaitEvent(s2, evFork, 0);
    k_init_deg<<<(n + T - 1) / T, T, 0, s2>>>(n);                       // 0
    k_deg_scatter<<<(e4t + T - 1) / T, T, 0, s2>>>(dst, e);             // 1
    cudaEventRecord(evJoin, s2);

    k_xw1_raw<<<(n + 64 * XW_ND - 1) / (64 * XW_ND), T>>>(x, W1, n);    // 2

    // Join, then scale + rest of the chain on the main stream.
    cudaStreamWaitEvent(0, evJoin, 0);
    k_scale<<<((long long)n * 4 + T - 1) / T, T>>>(n);                  // 3 (profiled)
    {
        long long total = (long long)((e + 1) >> 1) * 4;
        k_edge1<<<(unsigned)((total + T - 1) / T), T>>>(src, dst, e);   // 4
    }
    k_layer2<<<((long long)n * NCLS + T - 1) / T, T>>>(b1, W2, n);      // 5
    {
        long long total = (long long)((e + 1) >> 1) * 2;
        k_edge2<<<(unsigned)((total + T - 1) / T), T>>>(src, dst, e);   // 6
    }
    k_logsoftmax<<<(n + T - 1) / T, T>>>(b2, out, n);                   // 7
}

// round 14
// speedup vs baseline: 1.0899x; 1.0577x over previous
#include <cuda_runtime.h>
#include <cuda_fp16.h>
#include <stdint.h>

#define F_IN 128
#define HID  16
#define NCLS 8
#define MAX_N 100000

__device__ float  g_deg [MAX_N];
__device__ float  g_dinv[MAX_N];
__device__ __half g_h1h [MAX_N * HID];   // fp16 dinv*(x@W1) — gather side
__device__ float  g_agg1[MAX_N * HID];   // fp32 accumulator (self-loop init)
__device__ __half g_h2h [MAX_N * NCLS];  // fp16 dinv*h2 — gather side
__device__ float  g_agg2[MAX_N * NCLS];

__device__ __forceinline__ void red_add_v4(float* p, float4 v) {
    asm volatile("red.global.add.v4.f32 [%0], {%1, %2, %3, %4};"
                 :: "l"(p), "f"(v.x), "f"(v.y), "f"(v.z), "f"(v.w) : "memory");
}

// 0) deg init: self-loop contributes 1
__global__ void k_init_deg(int n) {
    int i = blockIdx.x * blockDim.x + threadIdx.x;
    if (i < n) g_deg[i] = 1.0f;
}

// 1) degree scatter, int4-vectorized (4 edges per thread)
__global__ void k_deg_scatter(const int* __restrict__ dst, int e) {
    int i = blockIdx.x * blockDim.x + threadIdx.x;
    int e4 = e >> 2;
    if (i < e4) {
        int4 d = ((const int4*)dst)[i];
        atomicAdd(&g_deg[d.x], 1.0f);
        atomicAdd(&g_deg[d.y], 1.0f);
        atomicAdd(&g_deg[d.z], 1.0f);
        atomicAdd(&g_deg[d.w], 1.0f);
    } else {
        int base = e4 * 4 + (i - e4);
        if (base < e) atomicAdd(&g_deg[dst[base]], 1.0f);
    }
}

// 2) xw1 fused (dinv inline): thread = (slot, jg), 4 nodes x 4 outputs.
//    agg1 = fp32 self term; h1h = fp16 copy for edge gathers.
#define XW_ND 4
__global__ void __launch_bounds__(256, 4) k_xw1(const float* __restrict__ x,
                                                const float* __restrict__ W1, int n) {
    __shared__ float4 sW1[F_IN * 4];  // sW1[k*4+jg] = W1[k][4jg..4jg+3]
    int t = threadIdx.x;
    for (int i = t; i < F_IN * 4; i += blockDim.x)
        sW1[i] = ((const float4*)W1)[i];
    __syncthreads();

    int slot = t >> 2;            // 0..63
    int jg   = t & 3;             // 0..3
    int base = blockIdx.x * (64 * XW_ND);

    int  node[XW_ND];
    bool ok  [XW_ND];
    #pragma unroll
    for (int i = 0; i < XW_ND; i++) {
        node[i] = base + i * 64 + slot;
        ok[i]   = node[i] < n;
    }

    float4 acc[XW_ND];
    #pragma unroll
    for (int i = 0; i < XW_ND; i++) acc[i] = make_float4(0.f, 0.f, 0.f, 0.f);

    #pragma unroll 4
    for (int k4 = 0; k4 < F_IN / 4; k4++) {
        float4 w0 = sW1[(k4 * 4 + 0) * 4 + jg];
        float4 w1 = sW1[(k4 * 4 + 1) * 4 + jg];
        float4 w2 = sW1[(k4 * 4 + 2) * 4 + jg];
        float4 w3 = sW1[(k4 * 4 + 3) * 4 + jg];
        float4 xv[XW_ND];
        #pragma unroll
        for (int i = 0; i < XW_ND; i++)
            xv[i] = ok[i] ? __ldg((const float4*)(x + (size_t)node[i] * F_IN) + k4)
                          : make_float4(0.f, 0.f, 0.f, 0.f);
        #pragma unroll
        for (int i = 0; i < XW_ND; i++) {
            acc[i].x = fmaf(xv[i].x, w0.x, acc[i].x);
            acc[i].y = fmaf(xv[i].x, w0.y, acc[i].y);
            acc[i].z = fmaf(xv[i].x, w0.z, acc[i].z);
            acc[i].w = fmaf(xv[i].x, w0.w, acc[i].w);
            acc[i].x = fmaf(xv[i].y, w1.x, acc[i].x);
            acc[i].y = fmaf(xv[i].y, w1.y, acc[i].y);
            acc[i].z = fmaf(xv[i].y, w1.z, acc[i].z);
            acc[i].w = fmaf(xv[i].y, w1.w, acc[i].w);
            acc[i].x = fmaf(xv[i].z, w2.x, acc[i].x);
            acc[i].y = fmaf(xv[i].z, w2.y, acc[i].y);
            acc[i].z = fmaf(xv[i].z, w2.z, acc[i].z);
            acc[i].w = fmaf(xv[i].z, w2.w, acc[i].w);
            acc[i].x = fmaf(xv[i].w, w3.x, acc[i].x);
            acc[i].y = fmaf(xv[i].w, w3.y, acc[i].y);
            acc[i].z = fmaf(xv[i].w, w3.z, acc[i].z);
            acc[i].w = fmaf(xv[i].w, w3.w, acc[i].w);
        }
    }

    #pragma unroll
    for (int i = 0; i < XW_ND; i++) {
        if (!ok[i]) continue;
        float di = rsqrtf(g_deg[node[i]]);
        if (jg == 0) g_dinv[node[i]] = di;
        float4 hs = make_float4(di * acc[i].x, di * acc[i].y,
                                di * acc[i].z, di * acc[i].w);
        *(float4*)(g_agg1 + node[i] * HID + jg * 4) = hs;   // fp32 self term
        __half2 p0 = __floats2half2_rn(hs.x, hs.y);
        __half2 p1 = __floats2half2_rn(hs.z, hs.w);
        uint2 u;
        u.x = *(unsigned*)&p0;
        u.y = *(unsigned*)&p1;
        *(uint2*)(g_h1h + node[i] * HID + jg * 4) = u;      // fp16 gather copy
    }
}

// 3) layer-1 edge scatter: 4 threads/edge (j=0..3), 2 edges/thread.
//    fp16 LDG.64 gather (4 halves) -> fp32 v4 RED.  [profiled idx 3]
__global__ void k_edge1(const int* __restrict__ src,
                        const int* __restrict__ dst, int e) {
    int h = (e + 1) >> 1;
    long long gid = (long long)blockIdx.x * blockDim.x + threadIdx.x;
    int q = (int)(gid >> 2);
    int j = (int)(gid & 3);
    if (q >= h) return;
    int eA = q, eB = q + h;
    bool hasB = eB < e;

    int sA = src[eA], dA = dst[eA];
    int sB = 0, dB = 0;
    if (hasB) { sB = src[eB]; dB = dst[eB]; }

    uint2 pA = *(const uint2*)(g_h1h + sA * HID + j * 4);
    uint2 pB = hasB ? *(const uint2*)(g_h1h + sB * HID + j * 4)
                    : make_uint2(0, 0);

    {
        float2 f0 = __half22float2(*(__half2*)&pA.x);
        float2 f1 = __half22float2(*(__half2*)&pA.y);
        red_add_v4(g_agg1 + dA * HID + j * 4, make_float4(f0.x, f0.y, f1.x, f1.y));
    }
    if (hasB) {
        float2 f0 = __half22float2(*(__half2*)&pB.x);
        float2 f1 = __half22float2(*(__half2*)&pB.y);
        red_add_v4(g_agg1 + dB * HID + j * 4, make_float4(f0.x, f0.y, f1.x, f1.y));
    }
}

// 4) h2 = relu(dinv*agg1 + b1) @ W2; agg2 = fp32 self term; h2h = fp16 copy
__global__ void k_layer2(const float* __restrict__ b1,
                         const float* __restrict__ W2, int n) {
    __shared__ float sW2[HID * NCLS];
    __shared__ float sb1[HID];
    if (threadIdx.x < HID * NCLS) sW2[threadIdx.x] = W2[threadIdx.x];
    if (threadIdx.x < HID) sb1[threadIdx.x] = b1[threadIdx.x];
    __syncthreads();

    int gid = blockIdx.x * blockDim.x + threadIdx.x;
    int node = gid / NCLS;
    int c    = gid % NCLS;
    if (node >= n) return;

    float di = g_dinv[node];
    float acc = 0.0f;
    #pragma unroll
    for (int j = 0; j < HID; j++) {
        float v = fmaf(di, g_agg1[node * HID + j], sb1[j]);
        v = fmaxf(v, 0.0f);
        acc = fmaf(v, sW2[j * NCLS + c], acc);
    }
    float hs = di * acc;
    g_agg2[node * NCLS + c] = hs;
    g_h2h [node * NCLS + c] = __float2half_rn(hs);
}

// 5) layer-2 edge scatter: 2 threads/edge (j=0,1), 2 edges/thread.
//    fp16 LDG.64 gather -> fp32 v4 RED.
__global__ void k_edge2(const int* __restrict__ src,
                        const int* __restrict__ dst, int e) {
    int h = (e + 1) >> 1;
    long long gid = (long long)blockIdx.x * blockDim.x + threadIdx.x;
    int q = (int)(gid >> 1);
    int j = (int)(gid & 1);
    if (q >= h) return;
    int eA = q, eB = q + h;
    bool hasB = eB < e;

    int sA = src[eA], dA = dst[eA];
    int sB = 0, dB = 0;
    if (hasB) { sB = src[eB]; dB = dst[eB]; }

    uint2 pA = *(const uint2*)(g_h2h + sA * NCLS + j * 4);
    uint2 pB = hasB ? *(const uint2*)(g_h2h + sB * NCLS + j * 4)
                    : make_uint2(0, 0);

    {
        float2 f0 = __half22float2(*(__half2*)&pA.x);
        float2 f1 = __half22float2(*(__half2*)&pA.y);
        red_add_v4(g_agg2 + dA * NCLS + j * 4, make_float4(f0.x, f0.y, f1.x, f1.y));
    }
    if (hasB) {
        float2 f0 = __half22float2(*(__half2*)&pB.x);
        float2 f1 = __half22float2(*(__half2*)&pB.y);
        red_add_v4(g_agg2 + dB * NCLS + j * 4, make_float4(f0.x, f0.y, f1.x, f1.y));
    }
}

// 6) logits = dinv*agg2 + b2 -> log_softmax
__global__ void k_logsoftmax(const float* __restrict__ b2,
                             float* __restrict__ out, int n) {
    __shared__ float sb2[NCLS];
    if (threadIdx.x < NCLS) sb2[threadIdx.x] = b2[threadIdx.x];
    __syncthreads();

    int i = blockIdx.x * blockDim.x + threadIdx.x;
    if (i >= n) return;

    float di = g_dinv[i];
    float4 a = *(const float4*)(g_agg2 + i * NCLS);
    float4 b = *(const float4*)(g_agg2 + i * NCLS + 4);
    float z[NCLS] = {fmaf(di, a.x, sb2[0]), fmaf(di, a.y, sb2[1]),
                     fmaf(di, a.z, sb2[2]), fmaf(di, a.w, sb2[3]),
                     fmaf(di, b.x, sb2[4]), fmaf(di, b.y, sb2[5]),
                     fmaf(di, b.z, sb2[6]), fmaf(di, b.w, sb2[7])};
    float m = z[0];
    #pragma unroll
    for (int c = 1; c < NCLS; c++) m = fmaxf(m, z[c]);
    float sum = 0.0f;
    #pragma unroll
    for (int c = 0; c < NCLS; c++) sum += expf(z[c] - m);
    float lse = m + logf(sum);
    *(float4*)(out + i * NCLS)     = make_float4(z[0]-lse, z[1]-lse, z[2]-lse, z[3]-lse);
    *(float4*)(out + i * NCLS + 4) = make_float4(z[4]-lse, z[5]-lse, z[6]-lse, z[7]-lse);
}

// ---------------------------------------------------------------------------
extern "C" void kernel_launch(void* const* d_in, const int* in_sizes, int n_in,
                              void* d_out, int out_size) {
    const float* x  = (const float*)d_in[0];
    const int*   ei = (const int*)d_in[1];    // [2, E] int32
    const float* W1 = (const float*)d_in[2];
    const float* b1 = (const float*)d_in[3];
    const float* W2 = (const float*)d_in[4];
    const float* b2 = (const float*)d_in[5];
    float*       out = (float*)d_out;

    const int n = in_sizes[0] / F_IN;      // 100000
    const int e = in_sizes[1] / 2;         // 3200000
    const int* src = ei;
    const int* dst = ei + e;

    const int T = 256;
    int e4t = (e >> 2) + (e & 3);

    k_init_deg<<<(n + T - 1) / T, T>>>(n);                              // 0
    k_deg_scatter<<<(e4t + T - 1) / T, T>>>(dst, e);                    // 1
    k_xw1<<<(n + 64 * XW_ND - 1) / (64 * XW_ND), T>>>(x, W1, n);        // 2
    {
        long long total = (long long)((e + 1) >> 1) * 4;
        k_edge1<<<(unsigned)((total + T - 1) / T), T>>>(src, dst, e);   // 3 (profiled)
    }
    k_layer2<<<((long long)n * NCLS + T - 1) / T, T>>>(b1, W2, n);      // 4
    {
        long long total = (long long)((e + 1) >> 1) * 2;
        k_edge2<<<(unsigned)((total + T - 1) / T), T>>>(src, dst, e);   // 5
    }
    k_logsoftmax<<<(n + T - 1) / T, T>>>(b2, out, n);                   // 6
}